// round 5
// baseline (speedup 1.0000x reference)
#include <cuda_runtime.h>

// Problem dims (compile-time constants from the reference)
#define NDIM1 4000
#define NDIM2 4000
#define GDIM  8000
#define RDIM  20000
#define MM1   1200
#define MM2   1200
#define MMG   2400
#define MMR   6000

#define RPB  4      // rows per block in the pair kernel
#define TILE 512    // column tile staged in shared memory
#define TPB  256    // threads per block (pair kernel)

// ---------------- scratch (device globals; no allocation allowed) -----------
__device__ int d_cnt1[NDIM1];
__device__ int d_cnt2[NDIM2];
__device__ int d_cntg[GDIM];
__device__ int d_cntr[RDIM];

__device__ int d_uidx1[MM1]; __device__ int d_w1[MM1];
__device__ int d_uidx2[MM2]; __device__ int d_w2[MM2];
__device__ int d_uidxg[MMG]; __device__ int d_wg[MMG];
__device__ int d_uidxr[MMR]; __device__ int d_wr[MMR];

__device__ float4 d_Q1[MM1];   // (q0,q1,q2, row weight)
__device__ float4 d_Q2[MM2];
__device__ float4 d_Pg[MMG];   // (p0,p1,p2, col/row weight)
__device__ float4 d_Pr[MMR];
__device__ float  d_b1v[MM1];
__device__ float  d_b2v[MM2];

__device__ int    d_U[4];      // unique counts: u1, u2, ug, ur
__device__ double d_acc[5];    // l1sum, l2sum, l3raw, |Pg|^2, |Pr|^2

// ---------------- kernel 0: zero scratch ------------------------------------
__global__ void k_zero() {
    int t = blockIdx.x * blockDim.x + threadIdx.x;
    int stride = gridDim.x * blockDim.x;
    for (int i = t; i < NDIM1; i += stride) d_cnt1[i] = 0;
    for (int i = t; i < NDIM2; i += stride) d_cnt2[i] = 0;
    for (int i = t; i < GDIM;  i += stride) d_cntg[i] = 0;
    for (int i = t; i < RDIM;  i += stride) d_cntr[i] = 0;
    if (t < 5) d_acc[t] = 0.0;
    if (t < 4) d_U[t] = 0;
}

// ---------------- kernel 1: histogram the masks ------------------------------
__global__ void k_count(const int* __restrict__ m1, const int* __restrict__ m2,
                        const int* __restrict__ mg, const int* __restrict__ mr) {
    int t = blockIdx.x * blockDim.x + threadIdx.x;
    if (t < MM1)                         atomicAdd(&d_cnt1[m1[t]], 1);
    else if (t < MM1 + MM2)              atomicAdd(&d_cnt2[m2[t - MM1]], 1);
    else if (t < MM1 + MM2 + MMG)        atomicAdd(&d_cntg[mg[t - MM1 - MM2]], 1);
    else if (t < MM1 + MM2 + MMG + MMR)  atomicAdd(&d_cntr[mr[t - MM1 - MM2 - MMG]], 1);
}

// ---------------- kernel 2: compact sorted-unique lists (single block) -------
__device__ void compact_axis(const int* cnt, int n, int* uidx, int* uw,
                             int* ucount, int* sh) {
    int tid = threadIdx.x;
    int carry = 0;
    for (int base = 0; base < n; base += 1024) {
        int v = base + tid;
        int ind = (v < n && cnt[v] > 0) ? 1 : 0;
        sh[tid] = ind;
        __syncthreads();
        // Hillis-Steele inclusive scan
        for (int off = 1; off < 1024; off <<= 1) {
            int tmp = (tid >= off) ? sh[tid - off] : 0;
            __syncthreads();
            sh[tid] += tmp;
            __syncthreads();
        }
        if (ind) {
            int pos = carry + sh[tid] - 1;
            uidx[pos] = v;
            uw[pos]   = cnt[v];
        }
        carry += sh[1023];
        __syncthreads();
    }
    if (tid == 0) *ucount = carry;
    __syncthreads();
}

__global__ void k_scan() {
    __shared__ int sh[1024];
    compact_axis(d_cnt1, NDIM1, d_uidx1, d_w1, &d_U[0], sh);
    compact_axis(d_cnt2, NDIM2, d_uidx2, d_w2, &d_U[1], sh);
    compact_axis(d_cntg, GDIM,  d_uidxg, d_wg, &d_U[2], sh);
    compact_axis(d_cntr, RDIM,  d_uidxr, d_wr, &d_U[3], sh);
}

// ---------------- kernel 3: softmax / Q projection / norms -------------------
__device__ __forceinline__ void softmax3(float c0, float c1, float c2,
                                         float& p0, float& p1, float& p2) {
    float m = fmaxf(c0, fmaxf(c1, c2));
    float e0 = expf(c0 - m), e1 = expf(c1 - m), e2 = expf(c2 - m);
    float inv = 1.0f / (e0 + e1 + e2);
    p0 = e0 * inv; p1 = e1 * inv; p2 = e2 * inv;
}

__global__ void k_pvals(const float* __restrict__ C1, const float* __restrict__ C2,
                        const float* __restrict__ Cg, const float* __restrict__ Cr,
                        const float* __restrict__ Ai,
                        const float* __restrict__ b1, const float* __restrict__ b2) {
    int t = blockIdx.x * blockDim.x + threadIdx.x;
    if (t < MM1) {
        if (t < d_U[0]) {
            int v = d_uidx1[t];
            float p0, p1, p2;
            softmax3(C1[v*3], C1[v*3+1], C1[v*3+2], p0, p1, p2);
            float q0 = p0*Ai[0] + p1*Ai[3] + p2*Ai[6];
            float q1 = p0*Ai[1] + p1*Ai[4] + p2*Ai[7];
            float q2 = p0*Ai[2] + p1*Ai[5] + p2*Ai[8];
            d_Q1[t]  = make_float4(q0, q1, q2, (float)d_w1[t]);
            d_b1v[t] = b1[v];
        }
    } else if (t < MM1 + MM2) {
        int u = t - MM1;
        if (u < d_U[1]) {
            int v = d_uidx2[u];
            float p0, p1, p2;
            softmax3(C2[v*3], C2[v*3+1], C2[v*3+2], p0, p1, p2);
            float q0 = p0*Ai[0] + p1*Ai[3] + p2*Ai[6];
            float q1 = p0*Ai[1] + p1*Ai[4] + p2*Ai[7];
            float q2 = p0*Ai[2] + p1*Ai[5] + p2*Ai[8];
            d_Q2[u]  = make_float4(q0, q1, q2, (float)d_w2[u]);
            d_b2v[u] = b2[v];
        }
    } else if (t < MM1 + MM2 + MMG) {
        int u = t - MM1 - MM2;
        if (u < d_U[2]) {
            int v = d_uidxg[u];
            float p0, p1, p2;
            softmax3(Cg[v*3], Cg[v*3+1], Cg[v*3+2], p0, p1, p2);
            float w = (float)d_wg[u];
            d_Pg[u] = make_float4(p0, p1, p2, w);
            atomicAdd(&d_acc[3], (double)(w * (p0*p0 + p1*p1 + p2*p2)));
        }
    } else if (t < MM1 + MM2 + MMG + MMR) {
        int u = t - MM1 - MM2 - MMG;
        if (u < d_U[3]) {
            int v = d_uidxr[u];
            float p0, p1, p2;
            softmax3(Cr[v*3], Cr[v*3+1], Cr[v*3+2], p0, p1, p2);
            float w = (float)d_wr[u];
            d_Pr[u] = make_float4(p0, p1, p2, w);
            atomicAdd(&d_acc[4], (double)(w * (p0*p0 + p1*p1 + p2*p2)));
        }
    }
}

// ---------------- kernel 4: fused gather-pair loss kernel --------------------
// Blocks [0,300)   : loss1 over G  (rows = unique mask_1, cols = unique mask_g)
// Blocks [300,600) : loss2 over R  (rows = unique mask_2, cols = unique mask_r)
// Blocks [600,1200): loss3 over A  (rows = unique mask_g, cols = unique mask_r)
__global__ void k_pair(const float* __restrict__ Gm, const float* __restrict__ Rm,
                       const float* __restrict__ Am,
                       const float* __restrict__ bg, const float* __restrict__ br) {
    __shared__ int    s_idx[TILE];
    __shared__ float4 s_pv[TILE];
    __shared__ float  s_red[TPB];

    const int B0 = (MM1 + RPB - 1) / RPB;   // 300
    const int B1 = (MM2 + RPB - 1) / RPB;   // 300

    int bid = blockIdx.x;
    int task, row0;
    const float*  mat;  long ld;  const float* cbias;
    const int*    ruidx; const float4* rq; const float* rb;
    int nrows; const int* cidx; const float4* cpv; int ncols;
    double* accp;

    if (bid < B0) {
        task = 0; row0 = bid * RPB;
        mat = Gm; ld = GDIM; cbias = bg;
        ruidx = d_uidx1; rq = d_Q1; rb = d_b1v; nrows = d_U[0];
        cidx = d_uidxg; cpv = d_Pg; ncols = d_U[2]; accp = &d_acc[0];
    } else if (bid < B0 + B1) {
        task = 1; row0 = (bid - B0) * RPB;
        mat = Rm; ld = RDIM; cbias = br;
        ruidx = d_uidx2; rq = d_Q2; rb = d_b2v; nrows = d_U[1];
        cidx = d_uidxr; cpv = d_Pr; ncols = d_U[3]; accp = &d_acc[1];
    } else {
        task = 2; row0 = (bid - B0 - B1) * RPB;
        mat = Am; ld = RDIM; cbias = nullptr;
        ruidx = d_uidxg; rq = d_Pg; rb = nullptr; nrows = d_U[2];
        cidx = d_uidxr; cpv = d_Pr; ncols = d_U[3]; accp = &d_acc[2];
    }

    int tid = threadIdx.x;

    const float* rp[RPB];
    float4 q[RPB];
    float  rbias[RPB];
    float  wrow[RPB];
#pragma unroll
    for (int r = 0; r < RPB; r++) {
        int u = row0 + r;
        bool valid = (u < nrows);
        int idx = valid ? ruidx[u] : 0;           // clamp: safe load, zero weight
        rp[r] = mat + (long)idx * ld;
        float4 qq = valid ? rq[u] : make_float4(0.f, 0.f, 0.f, 0.f);
        q[r] = qq;
        wrow[r] = valid ? qq.w : 0.f;
        rbias[r] = (valid && rb != nullptr) ? rb[u] : 0.f;
    }

    float acc[RPB] = {0.f, 0.f, 0.f, 0.f};

    for (int t0 = 0; t0 < ncols; t0 += TILE) {
        int tlen = min(TILE, ncols - t0);
        for (int j = tid; j < tlen; j += TPB) {
            s_idx[j] = cidx[t0 + j];
            s_pv[j]  = cpv[t0 + j];
        }
        __syncthreads();

        if (task == 2) {
            for (int j = tid; j < tlen; j += TPB) {
                int c = s_idx[j]; float4 p = s_pv[j];
#pragma unroll
                for (int r = 0; r < RPB; r++) {
                    float x  = __ldg(rp[r] + c);
                    float dt = q[r].x * p.x + q[r].y * p.y + q[r].z * p.z;
                    acc[r] += p.w * x * dt;
                }
            }
        } else {
            for (int j = tid; j < tlen; j += TPB) {
                int c = s_idx[j]; float4 p = s_pv[j];
                float bc = __ldg(cbias + c);
#pragma unroll
                for (int r = 0; r < RPB; r++) {
                    float x = __ldg(rp[r] + c);
                    float pred = q[r].x * p.x + q[r].y * p.y + q[r].z * p.z;
                    float d = x - pred - bc - rbias[r];
                    acc[r] += p.w * d * d;
                }
            }
        }
        __syncthreads();
    }

    float tot = 0.f;
#pragma unroll
    for (int r = 0; r < RPB; r++) tot += wrow[r] * acc[r];

    s_red[tid] = tot;
    __syncthreads();
    for (int s = TPB / 2; s > 0; s >>= 1) {
        if (tid < s) s_red[tid] += s_red[tid + s];
        __syncthreads();
    }
    if (tid == 0) atomicAdd(accp, (double)s_red[0]);
}

// ---------------- kernel 5: finalize -----------------------------------------
__global__ void k_finalize(float* __restrict__ out) {
    double l1 = d_acc[0] / ((double)MM1 * (double)MMG);
    double l2 = d_acc[1] / ((double)MM2 * (double)MMR);
    double l3 = -d_acc[2] / sqrt(d_acc[3] * d_acc[4]);
    double t1 = 1000.0 * l1;
    double t2 = 1000.0 * l2;
    double t3 = 100.0  * l3;
    out[0] = (float)(t1 + t2 + t3);   // ALPHA[3] = 0 -> loss4 contributes nothing
    out[1] = (float)t1;
    out[2] = (float)t2;
    out[3] = (float)t3;
    out[4] = 0.0f;
}

// ---------------- launch ------------------------------------------------------
extern "C" void kernel_launch(void* const* d_in, const int* in_sizes, int n_in,
                              void* d_out, int out_size) {
    const float* G  = (const float*)d_in[0];
    const float* R  = (const float*)d_in[1];
    const float* A  = (const float*)d_in[2];
    const float* C1 = (const float*)d_in[3];
    const float* C2 = (const float*)d_in[4];
    const float* Cg = (const float*)d_in[5];
    const float* Cr = (const float*)d_in[6];
    const float* Ai = (const float*)d_in[7];
    const float* bg = (const float*)d_in[8];
    const float* br = (const float*)d_in[9];
    const float* b1 = (const float*)d_in[10];
    const float* b2 = (const float*)d_in[11];
    const int*   m1 = (const int*)d_in[12];
    const int*   m2 = (const int*)d_in[13];
    const int*   mg = (const int*)d_in[14];
    const int*   mr = (const int*)d_in[15];
    float* out = (float*)d_out;

    (void)in_sizes; (void)n_in; (void)out_size;

    const int nmask = MM1 + MM2 + MMG + MMR;            // 10800
    const int B0 = (MM1 + RPB - 1) / RPB;               // 300
    const int B1 = (MM2 + RPB - 1) / RPB;               // 300
    const int B2 = (MMG + RPB - 1) / RPB;               // 600

    k_zero<<<64, 256>>>();
    k_count<<<(nmask + 255) / 256, 256>>>(m1, m2, mg, mr);
    k_scan<<<1, 1024>>>();
    k_pvals<<<(nmask + 255) / 256, 256>>>(C1, C2, Cg, Cr, Ai, b1, b2);
    k_pair<<<B0 + B1 + B2, TPB>>>(G, R, A, bg, br);
    k_finalize<<<1, 1>>>(out);
}

// round 7
// speedup vs baseline: 2.1413x; 2.1413x over previous
#include <cuda_runtime.h>

// Problem dims (compile-time constants from the reference)
#define NDIM1 4000
#define NDIM2 4000
#define GDIM  8000
#define RDIM  20000
#define MM1   1200
#define MM2   1200
#define MMG   2400
#define MMR   6000

#define TPB      256
#define COLS_PER_THREAD 4
#define TILE_COLS (TPB * COLS_PER_THREAD)   // 1024

// pair-kernel grid decomposition
#define T0_CT 8
#define T0_RC 16
#define T0_ROWS_PER_CHUNK 75     // 16*75 = 1200
#define T1_CT 20
#define T1_RC 16
#define T1_ROWS_PER_CHUNK 75     // 16*75 = 1200
#define T2_CT 20
#define T2_RC 30
#define T2_ROWS_PER_CHUNK 80     // 30*80 = 2400
#define T0_B (T0_CT * T0_RC)     // 128
#define T1_B (T1_CT * T1_RC)     // 320
#define T2_B (T2_CT * T2_RC)     // 600
#define MAX_CHUNK 80

// ---------------- scratch (device globals; no allocation allowed) -----------
__device__ int    d_cntg[GDIM];
__device__ int    d_cntr[RDIM];
__device__ float4 d_gmeta[GDIM];   // (p0,p1,p2, w=count) per G column
__device__ float4 d_rmeta[RDIM];   // (p0,p1,p2, w=count) per R column
__device__ float4 d_rq1[MM1];      // (q0,q1,q2, b1)  per mask_1 entry
__device__ float4 d_rq2[MM2];      // (q0,q1,q2, b2)  per mask_2 entry
__device__ double d_T[3];          // pair-kernel scalar sums: T1, T2, T3
__device__ double d_sums[64];      // small analytic moments

// d_sums layout:
//  col side (G): base 0  : M6(0..5: 00,01,02,11,12,22), Sp(6..8), Sbp(9..11), Sb(12), Sbb(13), norm(14)
//  col side (R): base 16 : same
//  row side 1 :  base 32 : Q2(0..5), Sq(6..8), Sbq(9..11), Sb(12), Sbsq(13)
//  row side 2 :  base 48 : same

// ---------------- kernel 0: zero scratch ------------------------------------
__global__ void k_init() {
    int t = blockIdx.x * blockDim.x + threadIdx.x;
    int stride = gridDim.x * blockDim.x;
    for (int i = t; i < GDIM; i += stride) d_cntg[i] = 0;
    for (int i = t; i < RDIM; i += stride) d_cntr[i] = 0;
    if (t < 3)  d_T[t] = 0.0;
    if (t < 64) d_sums[t] = 0.0;
}

// ---------------- kernel 1: column histograms -------------------------------
__global__ void k_count(const int* __restrict__ mg, const int* __restrict__ mr) {
    int t = blockIdx.x * blockDim.x + threadIdx.x;
    if (t < MMG)            atomicAdd(&d_cntg[mg[t]], 1);
    else if (t < MMG + MMR) atomicAdd(&d_cntr[mr[t - MMG]], 1);
}

// ---------------- kernel 2: softmax + moments -------------------------------
__device__ __forceinline__ void softmax3(float c0, float c1, float c2,
                                         float& p0, float& p1, float& p2) {
    float m = fmaxf(c0, fmaxf(c1, c2));
    float e0 = expf(c0 - m), e1 = expf(c1 - m), e2 = expf(c2 - m);
    float inv = 1.0f / (e0 + e1 + e2);
    p0 = e0 * inv; p1 = e1 * inv; p2 = e2 * inv;
}

__device__ __forceinline__ float blk_reduce(float v, float* sh) {
    int tid = threadIdx.x;
    sh[tid] = v;
    __syncthreads();
    for (int s = TPB / 2; s > 0; s >>= 1) {
        if (tid < s) sh[tid] += sh[tid + s];
        __syncthreads();
    }
    float r = sh[0];
    __syncthreads();
    return r;
}

// segments: [0,32) G cols, [32,111) R cols, [111,116) rows1, [116,121) rows2
#define SEG_G_B  32
#define SEG_R_B  79
#define SEG_R1_B 5
#define SEG_R2_B 5

__global__ void k_meta(const float* __restrict__ C1, const float* __restrict__ C2,
                       const float* __restrict__ Cg, const float* __restrict__ Cr,
                       const float* __restrict__ Ai,
                       const float* __restrict__ bg, const float* __restrict__ br,
                       const float* __restrict__ b1, const float* __restrict__ b2,
                       const int* __restrict__ m1, const int* __restrict__ m2) {
    __shared__ float sh[TPB];
    int bid = blockIdx.x, tid = threadIdx.x;
    float ch[15];
#pragma unroll
    for (int i = 0; i < 15; i++) ch[i] = 0.f;
    int base;

    if (bid < SEG_G_B || bid < SEG_G_B + SEG_R_B) {
        // column segments
        bool isG = (bid < SEG_G_B);
        int c = isG ? (bid * TPB + tid) : ((bid - SEG_G_B) * TPB + tid);
        int dim = isG ? GDIM : RDIM;
        base = isG ? 0 : 16;
        if (c < dim) {
            const float* C  = isG ? Cg : Cr;
            const float* bb = isG ? bg : br;
            const int*   cc = isG ? d_cntg : d_cntr;
            float p0, p1, p2;
            softmax3(C[3*c], C[3*c+1], C[3*c+2], p0, p1, p2);
            float w = (float)cc[c];
            float bv = bb[c];
            float4 mv = make_float4(p0, p1, p2, w);
            if (isG) d_gmeta[c] = mv; else d_rmeta[c] = mv;
            ch[0] = w*p0*p0; ch[1] = w*p0*p1; ch[2] = w*p0*p2;
            ch[3] = w*p1*p1; ch[4] = w*p1*p2; ch[5] = w*p2*p2;
            ch[6] = w*p0; ch[7] = w*p1; ch[8] = w*p2;
            ch[9] = w*bv*p0; ch[10] = w*bv*p1; ch[11] = w*bv*p2;
            ch[12] = w*bv; ch[13] = w*bv*bv;
            ch[14] = w*(p0*p0 + p1*p1 + p2*p2);
        }
    } else {
        // row segments
        bool is1 = (bid < SEG_G_B + SEG_R_B + SEG_R1_B);
        int i = is1 ? ((bid - SEG_G_B - SEG_R_B) * TPB + tid)
                    : ((bid - SEG_G_B - SEG_R_B - SEG_R1_B) * TPB + tid);
        base = is1 ? 32 : 48;
        int cnt = is1 ? MM1 : MM2;
        if (i < cnt) {
            const int*   mm = is1 ? m1 : m2;
            const float* C  = is1 ? C1 : C2;
            const float* bb = is1 ? b1 : b2;
            int m = mm[i];
            float p0, p1, p2;
            softmax3(C[3*m], C[3*m+1], C[3*m+2], p0, p1, p2);
            float q0 = p0*Ai[0] + p1*Ai[3] + p2*Ai[6];
            float q1 = p0*Ai[1] + p1*Ai[4] + p2*Ai[7];
            float q2 = p0*Ai[2] + p1*Ai[5] + p2*Ai[8];
            float bv = bb[m];
            float4 rv = make_float4(q0, q1, q2, bv);
            if (is1) d_rq1[i] = rv; else d_rq2[i] = rv;
            ch[0] = q0*q0; ch[1] = q0*q1; ch[2] = q0*q2;
            ch[3] = q1*q1; ch[4] = q1*q2; ch[5] = q2*q2;
            ch[6] = q0; ch[7] = q1; ch[8] = q2;
            ch[9] = bv*q0; ch[10] = bv*q1; ch[11] = bv*q2;
            ch[12] = bv; ch[13] = bv*bv;
            ch[14] = 0.f;
        }
    }
#pragma unroll
    for (int i = 0; i < 15; i++) {
        float t = blk_reduce(ch[i], sh);
        if (tid == 0 && t != 0.f) atomicAdd(&d_sums[base + i], (double)t);
    }
}

// ---------------- kernel 3: fused dense pair-sum kernel ----------------------
// task 0: G [rows = mask_1 entries, cols dense GDIM]    -> T1 partial
// task 1: R [rows = mask_2 entries, cols dense RDIM]    -> T2 partial
// task 2: A [rows = mask_g entries, cols dense RDIM]    -> T3 partial
__global__ void __launch_bounds__(TPB)
k_pair(const float* __restrict__ Gm, const float* __restrict__ Rm,
       const float* __restrict__ Am,
       const float* __restrict__ bg, const float* __restrict__ br,
       const int* __restrict__ m1, const int* __restrict__ m2,
       const int* __restrict__ mg) {
    __shared__ int    s_m[MAX_CHUNK];
    __shared__ float4 s_rv[MAX_CHUNK];
    __shared__ float  s_red[TPB];

    int bid = blockIdx.x, tid = threadIdx.x;
    int task, ct, rc, chunk, nrows_total;
    const float* mat; long ld; const float* cbias; const float4* cmeta;

    if (bid < T0_B) {
        task = 0; ct = bid % T0_CT; rc = bid / T0_CT;
        chunk = T0_ROWS_PER_CHUNK; nrows_total = MM1;
        mat = Gm; ld = GDIM; cbias = bg; cmeta = d_gmeta;
    } else if (bid < T0_B + T1_B) {
        int b = bid - T0_B;
        task = 1; ct = b % T1_CT; rc = b / T1_CT;
        chunk = T1_ROWS_PER_CHUNK; nrows_total = MM2;
        mat = Rm; ld = RDIM; cbias = br; cmeta = d_rmeta;
    } else {
        int b = bid - T0_B - T1_B;
        task = 2; ct = b % T2_CT; rc = b / T2_CT;
        chunk = T2_ROWS_PER_CHUNK; nrows_total = MMG;
        mat = Am; ld = RDIM; cbias = nullptr; cmeta = d_rmeta;
    }

    int r0 = rc * chunk;
    int nr = min(chunk, nrows_total - r0);
    int dim = (int)ld;
    int c0 = ct * TILE_COLS + tid * COLS_PER_THREAD;
    bool colvalid = (c0 + COLS_PER_THREAD <= dim);   // dims are multiples of 4

    // stage row metadata into smem
    for (int j = tid; j < nr; j += TPB) {
        int rr = r0 + j;
        if (task == 0)      { s_m[j] = m1[rr]; s_rv[j] = d_rq1[rr]; }
        else if (task == 1) { s_m[j] = m2[rr]; s_rv[j] = d_rq2[rr]; }
        else                { int m = mg[rr]; s_m[j] = m; s_rv[j] = d_gmeta[m]; }
    }
    __syncthreads();

    float contrib = 0.f;

    if (colvalid) {
        if (task == 2) {
            float y0[4] = {0,0,0,0}, y1[4] = {0,0,0,0}, y2[4] = {0,0,0,0};
#pragma unroll 4
            for (int j = 0; j < nr; ++j) {
                const float4 x4 = *(const float4*)(mat + (size_t)s_m[j] * ld + c0);
                float4 rv = s_rv[j];
                float xx[4] = {x4.x, x4.y, x4.z, x4.w};
#pragma unroll
                for (int c = 0; c < 4; c++) {
                    y0[c] += rv.x * xx[c];
                    y1[c] += rv.y * xx[c];
                    y2[c] += rv.z * xx[c];
                }
            }
#pragma unroll
            for (int c = 0; c < 4; c++) {
                float4 cm = __ldg(&cmeta[c0 + c]);
                contrib += cm.w * (cm.x * y0[c] + cm.y * y1[c] + cm.z * y2[c]);
            }
        } else {
            float y0[4] = {0,0,0,0}, y1[4] = {0,0,0,0}, y2[4] = {0,0,0,0};
            float s1[4] = {0,0,0,0}, sq[4] = {0,0,0,0}, sb[4] = {0,0,0,0};
#pragma unroll 4
            for (int j = 0; j < nr; ++j) {
                const float4 x4 = *(const float4*)(mat + (size_t)s_m[j] * ld + c0);
                float4 rv = s_rv[j];
                float xx[4] = {x4.x, x4.y, x4.z, x4.w};
#pragma unroll
                for (int c = 0; c < 4; c++) {
                    float x = xx[c];
                    y0[c] += rv.x * x;
                    y1[c] += rv.y * x;
                    y2[c] += rv.z * x;
                    s1[c] += x;
                    sq[c] += x * x;
                    sb[c] += rv.w * x;
                }
            }
#pragma unroll
            for (int c = 0; c < 4; c++) {
                float4 cm = __ldg(&cmeta[c0 + c]);
                float bgv = __ldg(&cbias[c0 + c]);
                float dotv = cm.x * y0[c] + cm.y * y1[c] + cm.z * y2[c];
                contrib += cm.w * (sq[c] - 2.f * (dotv + bgv * s1[c] + sb[c]));
            }
        }
    }

    // block reduce -> one double atomic per block
    s_red[tid] = contrib;
    __syncthreads();
    for (int s = TPB / 2; s > 0; s >>= 1) {
        if (tid < s) s_red[tid] += s_red[tid + s];
        __syncthreads();
    }
    if (tid == 0) atomicAdd(&d_T[task], (double)s_red[0]);
}

// ---------------- kernel 4: finalize -----------------------------------------
__device__ __forceinline__ double contract6(const double* A, const double* B) {
    // symmetric 3x3 stored as (00,01,02,11,12,22)
    return A[0]*B[0] + A[3]*B[3] + A[5]*B[5]
         + 2.0 * (A[1]*B[1] + A[2]*B[2] + A[4]*B[4]);
}
__device__ __forceinline__ double dot3(const double* a, const double* b) {
    return a[0]*b[0] + a[1]*b[1] + a[2]*b[2];
}

__global__ void k_finalize(float* __restrict__ out) {
    const double* g  = &d_sums[0];
    const double* rr = &d_sums[16];
    const double* r1 = &d_sums[32];
    const double* r2 = &d_sums[48];

    // loss1: rows (q_i, b1_i, w=1), cols (p_j, bg_j, w_j) over G
    double s1 = d_T[0]
              + contract6(&r1[0], &g[0])
              + 2.0 * (dot3(&r1[6], &g[9]) + dot3(&r1[9], &g[6]))
              + ((double)MM1 * g[13] + 2.0 * r1[12] * g[12] + (double)MMG * r1[13]);
    double loss1 = s1 / ((double)MM1 * (double)MMG);

    double s2 = d_T[1]
              + contract6(&r2[0], &rr[0])
              + 2.0 * (dot3(&r2[6], &rr[9]) + dot3(&r2[9], &rr[6]))
              + ((double)MM2 * rr[13] + 2.0 * r2[12] * rr[12] + (double)MMR * r2[13]);
    double loss2 = s2 / ((double)MM2 * (double)MMR);

    double loss3 = -d_T[2] / sqrt(g[14] * rr[14]);

    double t1 = 1000.0 * loss1;
    double t2 = 1000.0 * loss2;
    double t3 = 100.0  * loss3;
    out[0] = (float)(t1 + t2 + t3);   // ALPHA[3] = 0 -> loss4 contributes nothing
    out[1] = (float)t1;
    out[2] = (float)t2;
    out[3] = (float)t3;
    out[4] = 0.0f;
}

// ---------------- launch ------------------------------------------------------
extern "C" void kernel_launch(void* const* d_in, const int* in_sizes, int n_in,
                              void* d_out, int out_size) {
    const float* G  = (const float*)d_in[0];
    const float* R  = (const float*)d_in[1];
    const float* A  = (const float*)d_in[2];
    const float* C1 = (const float*)d_in[3];
    const float* C2 = (const float*)d_in[4];
    const float* Cg = (const float*)d_in[5];
    const float* Cr = (const float*)d_in[6];
    const float* Ai = (const float*)d_in[7];
    const float* bg = (const float*)d_in[8];
    const float* br = (const float*)d_in[9];
    const float* b1 = (const float*)d_in[10];
    const float* b2 = (const float*)d_in[11];
    const int*   m1 = (const int*)d_in[12];
    const int*   m2 = (const int*)d_in[13];
    const int*   mg = (const int*)d_in[14];
    const int*   mr = (const int*)d_in[15];
    float* out = (float*)d_out;

    (void)in_sizes; (void)n_in; (void)out_size;

    k_init<<<64, 256>>>();
    k_count<<<(MMG + MMR + 255) / 256, 256>>>(mg, mr);
    k_meta<<<SEG_G_B + SEG_R_B + SEG_R1_B + SEG_R2_B, TPB>>>(
        C1, C2, Cg, Cr, Ai, bg, br, b1, b2, m1, m2);
    k_pair<<<T0_B + T1_B + T2_B, TPB>>>(G, R, A, bg, br, m1, m2, mg);
    k_finalize<<<1, 1>>>(out);
}

// round 11
// speedup vs baseline: 2.4828x; 1.1595x over previous
#include <cuda_runtime.h>

// Problem dims (compile-time constants from the reference)
#define NDIM1 4000
#define NDIM2 4000
#define GDIM  8000
#define RDIM  20000
#define MM1   1200
#define MM2   1200
#define MMG   2400
#define MMR   6000

#define TPB      256
#define COLS_PER_THREAD 4
#define TILE_COLS (TPB * COLS_PER_THREAD)   // 1024

// pair-kernel grid decomposition (col-tiles x row-chunks)
#define T0_CT 8
#define T0_RC 16
#define T1_CT 20
#define T1_RC 16
#define T2_CT 20
#define T2_RC 30
#define T0_B (T0_CT * T0_RC)     // 128
#define T1_B (T1_CT * T1_RC)     // 320
#define T2_B (T2_CT * T2_RC)     // 600
#define MAX_CHUNK 80             // >= ceil(unique rows / RC) for every task

// ---------------- scratch (device globals; no allocation allowed) -----------
// Invariant: all scratch is ZERO on entry to kernel_launch. Module load zeroes
// it initially; each kernel re-zeroes whatever it consumed, so every graph
// replay sees clean state without a dedicated init kernel.
__device__ int    d_cnt1[NDIM1];
__device__ int    d_cnt2[NDIM2];
__device__ int    d_cntg[GDIM];
__device__ int    d_cntr[RDIM];

__device__ float4 d_gmeta[GDIM];   // (p0,p1,p2, w=count) per G column (dense)
__device__ float4 d_rmeta[RDIM];   // (p0,p1,p2, w=count) per R column (dense)

// compacted unique rows (unordered)
__device__ int    d_r1i[MM1];  __device__ float4 d_r1v[MM1];  __device__ float d_r1b[MM1];
__device__ int    d_r2i[MM2];  __device__ float4 d_r2v[MM2];  __device__ float d_r2b[MM2];
__device__ int    d_rgi[MMG];  __device__ float4 d_rgv[MMG];

__device__ int    d_U[4];      // unique counts: rows1, rows2, rowsG
__device__ double d_T[3];      // pair-kernel scalar sums: T1, T2, T3
__device__ double d_sums[64];  // analytic moments

// d_sums layout:
//  col side (G): base 0  : M6(0..5: 00,01,02,11,12,22), Sp(6..8), Sbp(9..11), Sb(12), Sbb(13), norm(14)
//  col side (R): base 16 : same
//  row side 1 :  base 32 : Q2(0..5), Sq(6..8), Sbq(9..11), Sb(12), Sbb(13)
//  row side 2 :  base 48 : same

// ---------------- kernel 1: histograms for all four masks --------------------
__global__ void k_count(const int* __restrict__ m1, const int* __restrict__ m2,
                        const int* __restrict__ mg, const int* __restrict__ mr) {
    int t = blockIdx.x * blockDim.x + threadIdx.x;
    if (t < MM1)                         atomicAdd(&d_cnt1[m1[t]], 1);
    else if (t < MM1 + MM2)              atomicAdd(&d_cnt2[m2[t - MM1]], 1);
    else if (t < MM1 + MM2 + MMG)        atomicAdd(&d_cntg[mg[t - MM1 - MM2]], 1);
    else if (t < MM1 + MM2 + MMG + MMR)  atomicAdd(&d_cntr[mr[t - MM1 - MM2 - MMG]], 1);
}

// ---------------- kernel 2: compact + softmax + moments ----------------------
__device__ __forceinline__ void softmax3(float c0, float c1, float c2,
                                         float& p0, float& p1, float& p2) {
    float m = fmaxf(c0, fmaxf(c1, c2));
    float e0 = expf(c0 - m), e1 = expf(c1 - m), e2 = expf(c2 - m);
    float inv = 1.0f / (e0 + e1 + e2);
    p0 = e0 * inv; p1 = e1 * inv; p2 = e2 * inv;
}

__device__ __forceinline__ float warp_red(float v) {
    v += __shfl_down_sync(0xffffffffu, v, 16);
    v += __shfl_down_sync(0xffffffffu, v, 8);
    v += __shfl_down_sync(0xffffffffu, v, 4);
    v += __shfl_down_sync(0xffffffffu, v, 2);
    v += __shfl_down_sync(0xffffffffu, v, 1);
    return v;
}

// Padded segments (block-aligned so each block has one uniform moment base):
//  [0, 4096)        rows1 (NDIM1=4000 valid)    base 32
//  [4096, 8192)     rows2 (NDIM2=4000 valid)    base 48
//  [8192, 16384)    colsG (GDIM=8000 valid)     base 0
//  [16384, 36608)   colsR (RDIM=20000 valid)    base 16
#define SEG1_END  4096
#define SEG2_END  8192
#define SEGG_END  16384
#define SEGR_END  36608
#define COMPACT_BLOCKS (SEGR_END / TPB)   // 143

__global__ void k_compact(const float* __restrict__ C1, const float* __restrict__ C2,
                          const float* __restrict__ Cg, const float* __restrict__ Cr,
                          const float* __restrict__ Ai,
                          const float* __restrict__ bg, const float* __restrict__ br,
                          const float* __restrict__ b1, const float* __restrict__ b2) {
    __shared__ float s_mom[8][15];
    int t   = blockIdx.x * blockDim.x + threadIdx.x;
    int tid = threadIdx.x;
    int wid = tid >> 5, lane = tid & 31;

    float ch[15];
#pragma unroll
    for (int i = 0; i < 15; i++) ch[i] = 0.f;
    int base;

    if (t < SEG2_END) {
        // row segments
        bool is1 = (t < SEG1_END);
        int v = is1 ? t : (t - SEG1_END);
        base = is1 ? 32 : 48;
        int n = is1 ? NDIM1 : NDIM2;
        if (v < n) {
            int c;
            if (is1) { c = d_cnt1[v]; d_cnt1[v] = 0; }
            else     { c = d_cnt2[v]; d_cnt2[v] = 0; }
            if (c > 0) {
                const float* C  = is1 ? C1 : C2;
                const float* bb = is1 ? b1 : b2;
                float p0, p1, p2;
                softmax3(C[3*v], C[3*v+1], C[3*v+2], p0, p1, p2);
                float q0 = p0*Ai[0] + p1*Ai[3] + p2*Ai[6];
                float q1 = p0*Ai[1] + p1*Ai[4] + p2*Ai[7];
                float q2 = p0*Ai[2] + p1*Ai[5] + p2*Ai[8];
                float bv = bb[v];
                float w  = (float)c;
                int pos = atomicAdd(&d_U[is1 ? 0 : 1], 1);
                float4 rv = make_float4(w*q0, w*q1, w*q2, w);
                if (is1) { d_r1i[pos] = v; d_r1v[pos] = rv; d_r1b[pos] = w*bv; }
                else     { d_r2i[pos] = v; d_r2v[pos] = rv; d_r2b[pos] = w*bv; }
                ch[0] = w*q0*q0; ch[1] = w*q0*q1; ch[2] = w*q0*q2;
                ch[3] = w*q1*q1; ch[4] = w*q1*q2; ch[5] = w*q2*q2;
                ch[6] = w*q0; ch[7] = w*q1; ch[8] = w*q2;
                ch[9] = w*bv*q0; ch[10] = w*bv*q1; ch[11] = w*bv*q2;
                ch[12] = w*bv; ch[13] = w*bv*bv;
            }
        }
    } else {
        // column segments
        bool isG = (t < SEGG_END);
        int v = isG ? (t - SEG2_END) : (t - SEGG_END);
        base = isG ? 0 : 16;
        int n = isG ? GDIM : RDIM;
        if (v < n) {
            const float* C  = isG ? Cg : Cr;
            const float* bb = isG ? bg : br;
            int c;
            if (isG) { c = d_cntg[v]; d_cntg[v] = 0; }
            else     { c = d_cntr[v]; d_cntr[v] = 0; }
            float p0, p1, p2;
            softmax3(C[3*v], C[3*v+1], C[3*v+2], p0, p1, p2);
            float w  = (float)c;
            float bv = bb[v];
            float4 mv = make_float4(p0, p1, p2, w);
            if (isG) {
                d_gmeta[v] = mv;
                if (c > 0) {
                    int pos = atomicAdd(&d_U[2], 1);
                    d_rgi[pos] = v;
                    d_rgv[pos] = make_float4(w*p0, w*p1, w*p2, 0.f);
                }
            } else {
                d_rmeta[v] = mv;
            }
            if (c > 0) {
                ch[0] = w*p0*p0; ch[1] = w*p0*p1; ch[2] = w*p0*p2;
                ch[3] = w*p1*p1; ch[4] = w*p1*p2; ch[5] = w*p2*p2;
                ch[6] = w*p0; ch[7] = w*p1; ch[8] = w*p2;
                ch[9] = w*bv*p0; ch[10] = w*bv*p1; ch[11] = w*bv*p2;
                ch[12] = w*bv; ch[13] = w*bv*bv;
                ch[14] = w*(p0*p0 + p1*p1 + p2*p2);
            }
        }
    }

    // fast block reduce: warp shuffle -> smem -> 15 atomics/block
#pragma unroll
    for (int i = 0; i < 15; i++) {
        float r = warp_red(ch[i]);
        if (lane == 0) s_mom[wid][i] = r;
    }
    __syncthreads();
    if (tid < 15) {
        float tot = 0.f;
#pragma unroll
        for (int w = 0; w < 8; w++) tot += s_mom[w][tid];
        if (tot != 0.f) atomicAdd(&d_sums[base + tid], (double)tot);
    }
}

// ---------------- kernel 3: fused dense pair-sum kernel ----------------------
// task 0: G  rows = unique mask_1 (weighted), cols dense GDIM  -> T1 partial
// task 1: R  rows = unique mask_2 (weighted), cols dense RDIM  -> T2 partial
// task 2: A  rows = unique mask_g (weighted), cols dense RDIM  -> T3 partial
__device__ __forceinline__ float4 ldcs4(const float* p) {
    return __ldcs((const float4*)p);
}

__global__ void __launch_bounds__(TPB)
k_pair(const float* __restrict__ Gm, const float* __restrict__ Rm,
       const float* __restrict__ Am,
       const float* __restrict__ bg, const float* __restrict__ br) {
    __shared__ int    s_off[MAX_CHUNK];   // row element-offsets (idx*ld)
    __shared__ float4 s_rv[MAX_CHUNK];
    __shared__ float  s_wb[MAX_CHUNK];
    __shared__ float  s_red[TPB];

    int bid = blockIdx.x, tid = threadIdx.x;
    int task, ct, rc, RC;
    const float* mat; int ld; const float* cbias; const float4* cmeta;

    if (bid < T0_B) {
        task = 0; ct = bid % T0_CT; rc = bid / T0_CT; RC = T0_RC;
        mat = Gm; ld = GDIM; cbias = bg; cmeta = d_gmeta;
    } else if (bid < T0_B + T1_B) {
        int b = bid - T0_B;
        task = 1; ct = b % T1_CT; rc = b / T1_CT; RC = T1_RC;
        mat = Rm; ld = RDIM; cbias = br; cmeta = d_rmeta;
    } else {
        int b = bid - T0_B - T1_B;
        task = 2; ct = b % T2_CT; rc = b / T2_CT; RC = T2_RC;
        mat = Am; ld = RDIM; cbias = nullptr; cmeta = d_rmeta;
    }

    int u     = d_U[task];                 // unique row count (runtime)
    int chunk = (u + RC - 1) / RC;
    int r0    = rc * chunk;
    int nr    = min(chunk, u - r0);
    if (nr < 0) nr = 0;

    int c0 = ct * TILE_COLS + tid * COLS_PER_THREAD;
    bool colvalid = (c0 + COLS_PER_THREAD <= ld);   // dims are multiples of 4

    // stage row metadata into smem (precompute element offsets)
    for (int j = tid; j < nr; j += TPB) {
        int rr = r0 + j;
        if (task == 0)      { s_off[j] = d_r1i[rr] * GDIM; s_rv[j] = d_r1v[rr]; s_wb[j] = d_r1b[rr]; }
        else if (task == 1) { s_off[j] = d_r2i[rr] * RDIM; s_rv[j] = d_r2v[rr]; s_wb[j] = d_r2b[rr]; }
        else                { s_off[j] = d_rgi[rr] * RDIM; s_rv[j] = d_rgv[rr]; }
    }
    __syncthreads();

    float contrib = 0.f;

    if (colvalid) {
        if (task == 2) {
            float y0[4] = {0,0,0,0}, y1[4] = {0,0,0,0}, y2[4] = {0,0,0,0};
#pragma unroll 4
            for (int j = 0; j < nr; ++j) {
                const float4 x4 = ldcs4(mat + (size_t)(unsigned)s_off[j] + c0);
                float4 rv = s_rv[j];          // (w*p0, w*p1, w*p2, -)
                float xx[4] = {x4.x, x4.y, x4.z, x4.w};
#pragma unroll
                for (int c = 0; c < 4; c++) {
                    y0[c] += rv.x * xx[c];
                    y1[c] += rv.y * xx[c];
                    y2[c] += rv.z * xx[c];
                }
            }
#pragma unroll
            for (int c = 0; c < 4; c++) {
                float4 cm = __ldg(&cmeta[c0 + c]);   // (p0,p1,p2,w)
                contrib += cm.w * (cm.x * y0[c] + cm.y * y1[c] + cm.z * y2[c]);
            }
        } else {
            float y0[4] = {0,0,0,0}, y1[4] = {0,0,0,0}, y2[4] = {0,0,0,0};
            float s1[4] = {0,0,0,0}, sq[4] = {0,0,0,0}, sb[4] = {0,0,0,0};
#pragma unroll 4
            for (int j = 0; j < nr; ++j) {
                const float4 x4 = ldcs4(mat + (size_t)(unsigned)s_off[j] + c0);
                float4 rv = s_rv[j];          // (w*q0, w*q1, w*q2, w)
                float wb  = s_wb[j];          // w*b
                float xx[4] = {x4.x, x4.y, x4.z, x4.w};
#pragma unroll
                for (int c = 0; c < 4; c++) {
                    float x = xx[c];
                    y0[c] += rv.x * x;
                    y1[c] += rv.y * x;
                    y2[c] += rv.z * x;
                    float tw = rv.w * x;
                    s1[c] += tw;
                    sq[c] += tw * x;
                    sb[c] += wb * x;
                }
            }
#pragma unroll
            for (int c = 0; c < 4; c++) {
                float4 cm = __ldg(&cmeta[c0 + c]);
                float bgv = __ldg(&cbias[c0 + c]);
                float dotv = cm.x * y0[c] + cm.y * y1[c] + cm.z * y2[c];
                contrib += cm.w * (sq[c] - 2.f * (dotv + bgv * s1[c] + sb[c]));
            }
        }
    }

    // block reduce -> one double atomic per block
    s_red[tid] = contrib;
    __syncthreads();
    for (int s = TPB / 2; s > 0; s >>= 1) {
        if (tid < s) s_red[tid] += s_red[tid + s];
        __syncthreads();
    }
    if (tid == 0) atomicAdd(&d_T[task], (double)s_red[0]);
}

// ---------------- kernel 4: finalize (+ reset scalar scratch) ----------------
__device__ __forceinline__ double contract6(const double* A, const double* B) {
    // symmetric 3x3 stored as (00,01,02,11,12,22)
    return A[0]*B[0] + A[3]*B[3] + A[5]*B[5]
         + 2.0 * (A[1]*B[1] + A[2]*B[2] + A[4]*B[4]);
}
__device__ __forceinline__ double dot3(const double* a, const double* b) {
    return a[0]*b[0] + a[1]*b[1] + a[2]*b[2];
}

__global__ void k_finalize(float* __restrict__ out) {
    const double* g  = &d_sums[0];
    const double* rr = &d_sums[16];
    const double* r1 = &d_sums[32];
    const double* r2 = &d_sums[48];

    double s1 = d_T[0]
              + contract6(&r1[0], &g[0])
              + 2.0 * (dot3(&r1[6], &g[9]) + dot3(&r1[9], &g[6]))
              + ((double)MM1 * g[13] + 2.0 * r1[12] * g[12] + (double)MMG * r1[13]);
    double loss1 = s1 / ((double)MM1 * (double)MMG);

    double s2 = d_T[1]
              + contract6(&r2[0], &rr[0])
              + 2.0 * (dot3(&r2[6], &rr[9]) + dot3(&r2[9], &rr[6]))
              + ((double)MM2 * rr[13] + 2.0 * r2[12] * rr[12] + (double)MMR * r2[13]);
    double loss2 = s2 / ((double)MM2 * (double)MMR);

    double loss3 = -d_T[2] / sqrt(g[14] * rr[14]);

    double t1 = 1000.0 * loss1;
    double t2 = 1000.0 * loss2;
    double t3 = 100.0  * loss3;
    out[0] = (float)(t1 + t2 + t3);   // ALPHA[3] = 0 -> loss4 contributes nothing
    out[1] = (float)t1;
    out[2] = (float)t2;
    out[3] = (float)t3;
    out[4] = 0.0f;

    // reset scalar scratch for the next graph replay
    for (int i = 0; i < 64; i++) d_sums[i] = 0.0;
    d_T[0] = 0.0; d_T[1] = 0.0; d_T[2] = 0.0;
    d_U[0] = 0; d_U[1] = 0; d_U[2] = 0; d_U[3] = 0;
}

// ---------------- launch ------------------------------------------------------
extern "C" void kernel_launch(void* const* d_in, const int* in_sizes, int n_in,
                              void* d_out, int out_size) {
    const float* G  = (const float*)d_in[0];
    const float* R  = (const float*)d_in[1];
    const float* A  = (const float*)d_in[2];
    const float* C1 = (const float*)d_in[3];
    const float* C2 = (const float*)d_in[4];
    const float* Cg = (const float*)d_in[5];
    const float* Cr = (const float*)d_in[6];
    const float* Ai = (const float*)d_in[7];
    const float* bg = (const float*)d_in[8];
    const float* br = (const float*)d_in[9];
    const float* b1 = (const float*)d_in[10];
    const float* b2 = (const float*)d_in[11];
    const int*   m1 = (const int*)d_in[12];
    const int*   m2 = (const int*)d_in[13];
    const int*   mg = (const int*)d_in[14];
    const int*   mr = (const int*)d_in[15];
    float* out = (float*)d_out;

    (void)in_sizes; (void)n_in; (void)out_size;

    const int nmask = MM1 + MM2 + MMG + MMR;   // 10800

    k_count<<<(nmask + 255) / 256, 256>>>(m1, m2, mg, mr);
    k_compact<<<COMPACT_BLOCKS, TPB>>>(C1, C2, Cg, Cr, Ai, bg, br, b1, b2);
    k_pair<<<T0_B + T1_B + T2_B, TPB>>>(G, R, A, bg, br);
    k_finalize<<<1, 1>>>(out);
}